// round 12
// baseline (speedup 1.0000x reference)
#include <cuda_runtime.h>
#include <cuda_fp16.h>
#include <math.h>

#define TPB 256
#define MAXK 128
#define QCAP 512

// Per-block partials: [(b*gx+bx)*4 + {stc,str,cnt,pad}]. Every used slot is
// written each run, so no zeroing kernel is needed.
__device__ float g_part[65536];
// Wrap-around completion counter: returns to 0 after every full run, so graph
// replays are deterministic without an init kernel.
__device__ unsigned g_ctr = 0;

#define C4 0.2857142857f      /* 0.4/1.4 */
#define SCREEN_ERR 6e-3f      /* conservative abs error bound of fp16 screen */

__device__ __forceinline__ unsigned h2_as_u32(__half2 h) {
    unsigned u;
    *reinterpret_cast<__half2*>(&u) = h;
    return u;
}
__device__ __forceinline__ __half2 u32_as_h2(unsigned u) {
    return *reinterpret_cast<__half2*>(&u);
}

__device__ __forceinline__ float softplusf(float z) {
    return fmaxf(z, 0.f) + __logf(1.f + __expf(-fabsf(z)));
}

template<int KFIX>
__global__ __launch_bounds__(TPB) void loss_kernel(
    const float* __restrict__ prop,     // (B, A, 6)
    const float* __restrict__ anchors,  // (A, 4) xywh
    const float* __restrict__ gt,       // (B, K, 4) xywh
    float* __restrict__ out,
    int A, int Krt, int totalBlocks)
{
    const int K = (KFIX > 0) ? KFIX : Krt;
    __shared__ float4 s_g[MAXK];          // gt boxes xyxy (fp32, for pass-2)
    __shared__ float  s_ga[MAXK];         // gt areas (fp32, for pass-2)
    __shared__ uint4  s_gh[MAXK];         // half2 [x1,x1][y1,y1][x2,x2][y2,y2]
    __shared__ unsigned s_ng4[MAXK];      // half2 [-C4*ga, -C4*ga] as u32
    __shared__ int    s_q[QCAP];          // queued anchor ids (pass-2 decides)
    __shared__ int    s_qc;
    __shared__ float  r0[8], r1[8], r2[8];
    __shared__ int    s_last;
    __shared__ float  s_fin[8][4];

    const int b  = blockIdx.y;
    const int gx = gridDim.x;

    if (threadIdx.x == 0) s_qc = 0;
    for (int k = threadIdx.x; k < K; k += TPB) {
        const float* g = gt + ((size_t)b * K + k) * 4;
        float x0 = g[0], y0 = g[1], w = g[2], h = g[3];
        float x2 = x0 + w, y2 = y0 + h;
        s_g[k]  = make_float4(x0, y0, x2, y2);
        float ga = w * h;
        s_ga[k] = ga;
        uint4 u;
        u.x = h2_as_u32(__float2half2_rn(x0));
        u.y = h2_as_u32(__float2half2_rn(y0));
        u.z = h2_as_u32(__float2half2_rn(x2));
        u.w = h2_as_u32(__float2half2_rn(y2));
        s_gh[k]  = u;
        s_ng4[k] = h2_as_u32(__float2half2_rn(-C4 * ga));
    }
    __syncthreads();

    // ---- fp16x2 screen: 2 anchors per thread packed in half2 lanes ----
    const int a0 = blockIdx.x * (2 * TPB) + threadIdx.x;
    const int a1 = a0 + TPB;
    const int c0 = min(a0, A - 1);
    const int c1 = min(a1, A - 1);

    const float4 an0 = reinterpret_cast<const float4*>(anchors)[c0];
    const float4 an1 = reinterpret_cast<const float4*>(anchors)[c1];
    const float xl0 = __ldg(prop + ((size_t)b * A + c0) * 6 + 4);
    const float xl1 = __ldg(prop + ((size_t)b * A + c1) * 6 + 4);

    const float areaA0 = an0.z * an0.w;
    const float areaA1 = an1.z * an1.w;

    const __half2 ax1h = __halves2half2(__float2half_rn(an0.x),
                                        __float2half_rn(an1.x));
    const __half2 ay1h = __halves2half2(__float2half_rn(an0.y),
                                        __float2half_rn(an1.y));
    const __half2 ax2h = __halves2half2(__float2half_rn(an0.x + an0.z),
                                        __float2half_rn(an1.x + an1.z));
    const __half2 ay2h = __halves2half2(__float2half_rn(an0.y + an0.w),
                                        __float2half_rn(an1.y + an1.w));
    const __half2 zero2 = __float2half2_rn(0.f);

    // M4 = max_k( inter_k - C4*ga_k ) in fp16x2, both anchors at once.
    // Inline-negative ONLY when M4 + SCREEN_ERR < C4*areaA (guarantees the
    // exact max-iou < 0.4). Everything else goes to the exact fp32 pass-2,
    // which resolves neg/ignore/pos identically to the reference.
    __half2 M4h = __float2half2_rn(-100.f);

#pragma unroll 4
    for (int k = 0; k < K; k++) {
        uint4 u = s_gh[k];
        __half2 ng4 = u32_as_h2(s_ng4[k]);
        __half2 wmin = __hmin2(ax2h, u32_as_h2(u.z));
        __half2 wmax = __hmax2(ax1h, u32_as_h2(u.x));
        __half2 hmin = __hmin2(ay2h, u32_as_h2(u.w));
        __half2 hmax = __hmax2(ay1h, u32_as_h2(u.y));
        __half2 w = __hsub2(wmin, wmax);
        __half2 h = __hsub2(hmin, hmax);
        __half2 wc = __hmax2(w, zero2);          // h<0 terms <=0, harmless
        M4h = __hmax2(M4h, __hfma2(wc, h, ng4));
    }

    const float M4_0 = __low2float(M4h);
    const float M4_1 = __high2float(M4h);

    float stc = 0.f, strl = 0.f, cnt = 0.f;

    if (a0 < A) {
        if (M4_0 < C4 * areaA0 - SCREEN_ERR) {
            float sig = 1.f / (1.f + __expf(-xl0));
            stc += 0.75f * softplusf(xl0) * sig * sig;      // focal, t=0
        } else {
            s_q[atomicAdd(&s_qc, 1)] = a0;
        }
    }
    if (a1 < A) {
        if (M4_1 < C4 * areaA1 - SCREEN_ERR) {
            float sig = 1.f / (1.f + __expf(-xl1));
            stc += 0.75f * softplusf(xl1) * sig * sig;      // focal, t=0
        } else {
            s_q[atomicAdd(&s_qc, 1)] = a1;
        }
    }
    __syncthreads();

    // ---- pass-2: exact fp32 classification + argmax (verified path) ----
    const int qc = s_qc;
    for (int i = threadIdx.x; i < qc; i += TPB) {
        const int aq = s_q[i];
        const float4 aw = reinterpret_cast<const float4*>(anchors)[aq];
        const float qx1 = aw.x, qy1 = aw.y;
        const float qx2 = aw.x + aw.z, qy2 = aw.y + aw.w;
        const float qar = aw.z * aw.w;

        // division-free exact argmax (strict > keeps first max)
        float bI = 0.f, bS = 1.f; int bK = 0;
        for (int k = 0; k < K; k++) {
            float4 g = s_g[k];
            float w = fminf(qx2, g.z) - fmaxf(qx1, g.x);
            float h = fminf(qy2, g.w) - fmaxf(qy1, g.y);
            float inter = fmaxf(w, 0.f) * h;
            float S = qar + s_ga[k];
            bool cc = inter * bS > bI * S;
            bI = cc ? inter : bI;
            bS = cc ? S : bS;
            bK = cc ? k : bK;
        }
        const float ts = bI / (bS - bI);

        const float* p = prop + ((size_t)b * A + aq) * 6;
        const float x = p[4];
        const float sig = 1.f / (1.f + __expf(-x));
        if (ts >= 0.5f) {
            cnt += 1.f;
            float om = 1.f - sig;
            stc += 0.25f * softplusf(-x) * om * om;         // focal, t=1
            float2 q01 = *reinterpret_cast<const float2*>(p);
            float2 q23 = *reinterpret_cast<const float2*>(p + 2);
            float4 g = s_g[bK];
            float ew = fmaxf(fminf(q01.x + q23.x, g.z) - fmaxf(q01.x, g.x), 0.f);
            float eh = fmaxf(fminf(q01.y + q23.y, g.w) - fmaxf(q01.y, g.y), 0.f);
            float ei = ew * eh;
            float eiou = ei / ((q23.x * q23.y + s_ga[bK]) - ei);
            strl += -__logf(eiou + 0.01f);
        } else if (ts < 0.4f) {
            stc += 0.75f * softplusf(x) * sig * sig;        // focal, t=0
        }
        // ts in [0.4, 0.5): ignore — contributes nothing
    }

    // ---- block reduction of (stc, strl, cnt) ----
    const unsigned m = 0xFFFFFFFFu;
#pragma unroll
    for (int o = 16; o; o >>= 1) {
        stc  += __shfl_down_sync(m, stc,  o);
        strl += __shfl_down_sync(m, strl, o);
        cnt  += __shfl_down_sync(m, cnt,  o);
    }
    const int wid = threadIdx.x >> 5, lane = threadIdx.x & 31;
    if (lane == 0) { r0[wid] = stc; r1[wid] = strl; r2[wid] = cnt; }
    __syncthreads();
    if (threadIdx.x == 0) {
        float t0 = 0.f, t1 = 0.f, t2 = 0.f;
#pragma unroll
        for (int i = 0; i < TPB / 32; i++) { t0 += r0[i]; t1 += r1[i]; t2 += r2[i]; }
        int slot = (b * gx + blockIdx.x) * 4;
        g_part[slot + 0] = t0;
        g_part[slot + 1] = t1;
        g_part[slot + 2] = t2;
        __threadfence();
        unsigned old = atomicInc(&g_ctr, (unsigned)(totalBlocks - 1));
        s_last = (old == (unsigned)(totalBlocks - 1)) ? 1 : 0;
    }
    __syncthreads();

    if (s_last) {
        const int B = gridDim.y;
        const int nwarp = TPB / 32;
        if (threadIdx.x < 32) ((float*)s_fin)[threadIdx.x] = 0.f;
        __syncthreads();

        if (B <= nwarp) {
            const int wpb = nwarp / B;            // warps per batch
            const int bb = wid / wpb;
            if (bb < B) {
                float f0 = 0.f, f1 = 0.f, f2 = 0.f;
                for (int blk = lane + 32 * (wid % wpb); blk < gx; blk += 32 * wpb) {
                    int s = (bb * gx + blk) * 4;
                    f0 += g_part[s + 0];
                    f1 += g_part[s + 1];
                    f2 += g_part[s + 2];
                }
#pragma unroll
                for (int o = 16; o; o >>= 1) {
                    f0 += __shfl_down_sync(m, f0, o);
                    f1 += __shfl_down_sync(m, f1, o);
                    f2 += __shfl_down_sync(m, f2, o);
                }
                if (lane == 0) {
                    atomicAdd(&s_fin[bb][0], f0);
                    atomicAdd(&s_fin[bb][1], f1);
                    atomicAdd(&s_fin[bb][2], f2);
                }
            }
            __syncthreads();
            if (threadIdx.x == 0) {
                float t = 0.f;
                for (int bb2 = 0; bb2 < B; bb2++) {
                    float cc = s_fin[bb2][2];
                    float safe = (cc > 0.f) ? cc : 1.f;
                    t += s_fin[bb2][0] / safe;
                    if (cc > 0.f) t += s_fin[bb2][1] / safe;
                }
                out[0] = t / (float)B;
            }
        } else if (threadIdx.x == 0) {
            // fallback (B > nwarp): serial, correctness only
            float t = 0.f;
            for (int bb2 = 0; bb2 < B; bb2++) {
                float f0 = 0.f, f1 = 0.f, f2 = 0.f;
                for (int blk = 0; blk < gx; blk++) {
                    int s = (bb2 * gx + blk) * 4;
                    f0 += g_part[s]; f1 += g_part[s + 1]; f2 += g_part[s + 2];
                }
                float safe = (f2 > 0.f) ? f2 : 1.f;
                t += f0 / safe;
                if (f2 > 0.f) t += f1 / safe;
            }
            out[0] = t / (float)B;
        }
    }
}

extern "C" void kernel_launch(void* const* d_in, const int* in_sizes, int n_in,
                              void* d_out, int out_size) {
    const float* prop    = (const float*)d_in[0];  // ss_proposal (B,A,6)
    const float* anchors = (const float*)d_in[1];  // anchors (A,4)
    const float* gt      = (const float*)d_in[2];  // ground_truth (B,K,4)

    const int A = in_sizes[1] / 4;
    const int B = in_sizes[0] / (A * 6);
    const int K = in_sizes[2] / (B * 4);

    const int gx = (A + 2 * TPB - 1) / (2 * TPB);   // 235 for A=120000
    dim3 grid(gx, B);
    const int total = gx * B;

    if (K == 64)
        loss_kernel<64><<<grid, TPB>>>(prop, anchors, gt, (float*)d_out, A, K, total);
    else
        loss_kernel<0><<<grid, TPB>>>(prop, anchors, gt, (float*)d_out, A, K, total);
}

// round 13
// speedup vs baseline: 1.1836x; 1.1836x over previous
#include <cuda_runtime.h>
#include <math.h>

#define TPB 256
#define MAXK 128

// Per-batch accumulators: [b*3 + {stc,str,cnt}]. Zero-initialized at load;
// the LAST block of every run resets them to zero after reading, so graph
// replays are deterministic with no init kernel.
__device__ float g_acc[16];
// Wrap-around completion counter (returns to 0 after each full run).
__device__ unsigned g_ctr = 0;

__device__ __forceinline__ float softplusf(float z) {
    // log(1 + exp(z)), stable
    return fmaxf(z, 0.f) + log1pf(__expf(-fabsf(z)));
}

__global__ __launch_bounds__(TPB) void loss_kernel(
    const float* __restrict__ prop,     // (B, A, 6)
    const float* __restrict__ anchors,  // (A, 4) xywh
    const float* __restrict__ gt,       // (B, K, 4) xywh
    float* __restrict__ out,
    int A, int K, int B, int totalBlocks)
{
    __shared__ float4 s_g[MAXK];   // gt boxes xyxy
    __shared__ float  s_ga[MAXK];  // gt areas
    __shared__ float  r0[8], r1[8], r2[8];
    __shared__ int    s_last;

    const int b = blockIdx.y;

    for (int k = threadIdx.x; k < K; k += TPB) {
        const float* g = gt + ((size_t)b * K + k) * 4;
        float gx = g[0], gy = g[1], gw = g[2], gh = g[3];
        s_g[k]  = make_float4(gx, gy, gx + gw, gy + gh);
        s_ga[k] = gw * gh;
    }
    __syncthreads();

    const int a = blockIdx.x * TPB + threadIdx.x;
    float stc = 0.f, strl = 0.f, cnt = 0.f;

    if (a < A) {
        float4 an = reinterpret_cast<const float4*>(anchors)[a];
        const float ax1 = an.x, ay1 = an.y;
        const float ax2 = an.x + an.z, ay2 = an.y + an.w;
        const float areaA = an.z * an.w;

        // division-free argmax (denominators strictly positive)
        float bI = 0.f, bD = 1.f;
        int   bK = 0;
#pragma unroll 8
        for (int k = 0; k < K; k++) {
            float4 g = s_g[k];
            float w = fminf(ax2, g.z) - fmaxf(ax1, g.x);
            float h = fminf(ay2, g.w) - fmaxf(ay1, g.y);
            w = fmaxf(w, 0.f);
            h = fmaxf(h, 0.f);
            float inter = w * h;
            float denom = (areaA + s_ga[k]) - inter;
            // iou_k > iou_best  <=>  inter*bD > bI*denom  (strict: keep first max)
            if (inter * bD > bI * denom) { bI = inter; bD = denom; bK = k; }
        }
        const float ts = bI / bD;  // target_score = max IoU

        const float* p = prop + ((size_t)b * A + a) * 6;
        float2 p01 = *reinterpret_cast<const float2*>(p);
        float2 p23 = *reinterpret_cast<const float2*>(p + 2);
        const float x = p[4];  // logit
        const float sig = 1.f / (1.f + __expf(-x));

        if (ts >= 0.5f) {
            cnt = 1.f;
            // focal with t=1: alpha * softplus(-x) * (1-p)^2
            float om = 1.f - sig;
            stc = 0.25f * softplusf(-x) * om * om;
            // elementwise IoU(pred box, matched gt box)
            float4 g = s_g[bK];
            float px2 = p01.x + p23.x, py2 = p01.y + p23.y;
            float ew = fmaxf(fminf(px2, g.z) - fmaxf(p01.x, g.x), 0.f);
            float eh = fmaxf(fminf(py2, g.w) - fmaxf(p01.y, g.y), 0.f);
            float ei = ew * eh;
            float eiou = ei / ((p23.x * p23.y + s_ga[bK]) - ei);
            strl = -__logf(eiou + 0.01f);
        } else if (ts < 0.4f) {
            // focal with t=0: (1-alpha) * softplus(x) * p^2
            stc = 0.75f * softplusf(x) * sig * sig;
        }
    }

    // block reduction of (stc, strl, cnt)
    const unsigned m = 0xFFFFFFFFu;
#pragma unroll
    for (int o = 16; o; o >>= 1) {
        stc  += __shfl_down_sync(m, stc,  o);
        strl += __shfl_down_sync(m, strl, o);
        cnt  += __shfl_down_sync(m, cnt,  o);
    }
    const int wid = threadIdx.x >> 5, lane = threadIdx.x & 31;
    if (lane == 0) { r0[wid] = stc; r1[wid] = strl; r2[wid] = cnt; }
    __syncthreads();

    if (threadIdx.x == 0) {
        float t0 = 0.f, t1 = 0.f, t2 = 0.f;
#pragma unroll
        for (int i = 0; i < TPB / 32; i++) { t0 += r0[i]; t1 += r1[i]; t2 += r2[i]; }
        // accumulate straight into the 12-float global accumulator
        atomicAdd(&g_acc[b * 3 + 0], t0);
        atomicAdd(&g_acc[b * 3 + 1], t1);
        atomicAdd(&g_acc[b * 3 + 2], t2);
        __threadfence();
        unsigned old = atomicInc(&g_ctr, (unsigned)(totalBlocks - 1));
        s_last = (old == (unsigned)(totalBlocks - 1)) ? 1 : 0;
    }
    __syncthreads();

    // last block: finalize (12 floats) and reset accumulators for next replay
    if (s_last && threadIdx.x == 0) {
        float t = 0.f;
        for (int bb = 0; bb < B; bb++) {
            float c = g_acc[bb * 3 + 2];
            float safe = (c > 0.f) ? c : 1.f;
            t += g_acc[bb * 3 + 0] / safe;                 // stc (undivided if no pos)
            if (c > 0.f) t += g_acc[bb * 3 + 1] / safe;    // str (0 if no pos)
        }
        out[0] = t / (float)B;
        for (int i = 0; i < 16; i++) g_acc[i] = 0.f;       // reset for determinism
    }
}

extern "C" void kernel_launch(void* const* d_in, const int* in_sizes, int n_in,
                              void* d_out, int out_size) {
    const float* prop    = (const float*)d_in[0];  // ss_proposal (B,A,6)
    const float* anchors = (const float*)d_in[1];  // anchors (A,4)
    const float* gt      = (const float*)d_in[2];  // ground_truth (B,K,4)

    const int A = in_sizes[1] / 4;
    const int B = in_sizes[0] / (A * 6);
    const int K = in_sizes[2] / (B * 4);

    const int gx = (A + TPB - 1) / TPB;     // 469 for A=120000
    dim3 grid(gx, B);
    const int total = gx * B;

    loss_kernel<<<grid, TPB>>>(prop, anchors, gt, (float*)d_out, A, K, B, total);
}

// round 14
// speedup vs baseline: 1.2654x; 1.0691x over previous
#include <cuda_runtime.h>
#include <math.h>

#define TPB 256
#define MAXK 128

// Per-batch accumulators: [b*3 + {stc,str,cnt}]. Zero-initialized at load;
// the LAST block of every run resets them to zero after reading, so graph
// replays are deterministic with no init kernel.
__device__ float g_acc[16];
// Wrap-around completion counter (returns to 0 after each full run).
__device__ unsigned g_ctr = 0;

__device__ __forceinline__ float softplusf(float z) {
    // log(1 + exp(z)), stable
    return fmaxf(z, 0.f) + log1pf(__expf(-fabsf(z)));
}

__global__ __launch_bounds__(TPB) void loss_kernel(
    const float* __restrict__ prop,     // (B, A, 6)
    const float* __restrict__ anchors,  // (A, 4) xywh
    const float* __restrict__ gt,       // (B, K, 4) xywh
    float* __restrict__ out,
    int A, int K, int B, int totalBlocks)
{
    __shared__ float4 s_g[MAXK];   // gt boxes xyxy
    __shared__ float  s_ga[MAXK];  // gt areas
    __shared__ float  r0[8], r1[8], r2[8];
    __shared__ int    s_last;

    const int b = blockIdx.y;

    for (int k = threadIdx.x; k < K; k += TPB) {
        const float* g = gt + ((size_t)b * K + k) * 4;
        float gx = g[0], gy = g[1], gw = g[2], gh = g[3];
        s_g[k]  = make_float4(gx, gy, gx + gw, gy + gh);
        s_ga[k] = gw * gh;
    }
    __syncthreads();

    const int a = blockIdx.x * TPB + threadIdx.x;
    float stc = 0.f, strl = 0.f, cnt = 0.f;

    if (a < A) {
        float4 an = reinterpret_cast<const float4*>(anchors)[a];
        const float ax1 = an.x, ay1 = an.y;
        const float ax2 = an.x + an.z, ay2 = an.y + an.w;
        const float areaA = an.z * an.w;

        // Division-free argmax in S-form (verified R2):
        //   iou_k > iou_best <=> inter_k*S_best > inter_best*S_k,
        //   S_k = areaA + ga[k] = inter + denom > 0. Strict > keeps first max.
        // Single clamp (verified R4): inter = max(w,0)*h. If h<0, inter<0 and
        // inter*bS < 0 <= bI*S can never win; when selected inter>0 => exact.
        float bI = 0.f, bS = 1.f;
        int   bK = 0;
#pragma unroll 8
        for (int k = 0; k < K; k++) {
            float4 g = s_g[k];
            float w = fminf(ax2, g.z) - fmaxf(ax1, g.x);
            float h = fminf(ay2, g.w) - fmaxf(ay1, g.y);
            float inter = fmaxf(w, 0.f) * h;
            float S = areaA + s_ga[k];
            if (inter * bS > bI * S) { bI = inter; bS = S; bK = k; }
        }
        const float ts = bI / (bS - bI);   // target_score = max IoU

        const float* p = prop + ((size_t)b * A + a) * 6;
        float2 p01 = *reinterpret_cast<const float2*>(p);
        float2 p23 = *reinterpret_cast<const float2*>(p + 2);
        const float x = p[4];  // logit
        const float sig = 1.f / (1.f + __expf(-x));

        if (ts >= 0.5f) {
            cnt = 1.f;
            // focal with t=1: alpha * softplus(-x) * (1-p)^2
            float om = 1.f - sig;
            stc = 0.25f * softplusf(-x) * om * om;
            // elementwise IoU(pred box, matched gt box)
            float4 g = s_g[bK];
            float px2 = p01.x + p23.x, py2 = p01.y + p23.y;
            float ew = fmaxf(fminf(px2, g.z) - fmaxf(p01.x, g.x), 0.f);
            float eh = fmaxf(fminf(py2, g.w) - fmaxf(p01.y, g.y), 0.f);
            float ei = ew * eh;
            float eiou = ei / ((p23.x * p23.y + s_ga[bK]) - ei);
            strl = -__logf(eiou + 0.01f);
        } else if (ts < 0.4f) {
            // focal with t=0: (1-alpha) * softplus(x) * p^2
            stc = 0.75f * softplusf(x) * sig * sig;
        }
    }

    // block reduction of (stc, strl, cnt)
    const unsigned m = 0xFFFFFFFFu;
#pragma unroll
    for (int o = 16; o; o >>= 1) {
        stc  += __shfl_down_sync(m, stc,  o);
        strl += __shfl_down_sync(m, strl, o);
        cnt  += __shfl_down_sync(m, cnt,  o);
    }
    const int wid = threadIdx.x >> 5, lane = threadIdx.x & 31;
    if (lane == 0) { r0[wid] = stc; r1[wid] = strl; r2[wid] = cnt; }
    __syncthreads();

    if (threadIdx.x == 0) {
        float t0 = 0.f, t1 = 0.f, t2 = 0.f;
#pragma unroll
        for (int i = 0; i < TPB / 32; i++) { t0 += r0[i]; t1 += r1[i]; t2 += r2[i]; }
        // accumulate straight into the 12-float global accumulator
        atomicAdd(&g_acc[b * 3 + 0], t0);
        atomicAdd(&g_acc[b * 3 + 1], t1);
        atomicAdd(&g_acc[b * 3 + 2], t2);
        __threadfence();
        unsigned old = atomicInc(&g_ctr, (unsigned)(totalBlocks - 1));
        s_last = (old == (unsigned)(totalBlocks - 1)) ? 1 : 0;
    }
    __syncthreads();

    // last block: finalize (12 floats) and reset accumulators for next replay
    if (s_last && threadIdx.x == 0) {
        float t = 0.f;
        for (int bb = 0; bb < B; bb++) {
            float c = g_acc[bb * 3 + 2];
            float safe = (c > 0.f) ? c : 1.f;
            t += g_acc[bb * 3 + 0] / safe;                 // stc (undivided if no pos)
            if (c > 0.f) t += g_acc[bb * 3 + 1] / safe;    // str (0 if no pos)
        }
        out[0] = t / (float)B;
        for (int i = 0; i < 16; i++) g_acc[i] = 0.f;       // reset for determinism
    }
}

extern "C" void kernel_launch(void* const* d_in, const int* in_sizes, int n_in,
                              void* d_out, int out_size) {
    const float* prop    = (const float*)d_in[0];  // ss_proposal (B,A,6)
    const float* anchors = (const float*)d_in[1];  // anchors (A,4)
    const float* gt      = (const float*)d_in[2];  // ground_truth (B,K,4)

    const int A = in_sizes[1] / 4;
    const int B = in_sizes[0] / (A * 6);
    const int K = in_sizes[2] / (B * 4);

    const int gx = (A + TPB - 1) / TPB;     // 469 for A=120000
    dim3 grid(gx, B);
    const int total = gx * B;

    loss_kernel<<<grid, TPB>>>(prop, anchors, gt, (float*)d_out, A, K, B, total);
}